// round 7
// baseline (speedup 1.0000x reference)
#include <cuda_runtime.h>
#include <cstdint>

#define N_NODES 50000
#define N_EDGES 800000
#define IN_DIM  256
#define OUT_DIM 64
#define NEG_SLOPE 0.01f
#define TILE_M 128

typedef unsigned long long ull;

// ---------------- device scratch ----------------
__device__ float g_z[N_NODES * OUT_DIM];     // 12.8 MB, L2-resident
__device__ float g_sl[N_NODES];
__device__ float g_sr[N_NODES];
__device__ float g_den[N_NODES];             // softmax denominators (atomic)
__device__ int   g_off[N_NODES + 1];         // CSR offsets (by dst)
__device__ int   g_cur[N_NODES];             // scatter cursors
__device__ ull   g_ep[N_EDGES];              // packed (exp(e)<<32 | src), dst-sorted

#define ADD2(a, b) asm("add.rn.f32x2 %0, %1, %2;" : "=l"(a) : "l"(a), "l"(b))

// ---------------- GEMM: z = h @ W + fused s_l/s_r ----------------
// 512 threads (16 warps -> 4/SMSP for latency hiding), TILE_M=128 rows.
// Thread tile: 4 row-pairs x 2 cols.
__global__ void __launch_bounds__(512, 1) gemm_kernel(const float* __restrict__ h,
                                                      const float* __restrict__ W,
                                                      const float* __restrict__ a_attn) {
    extern __shared__ float smem[];
    float*  Wsh = smem;                                 // [256][64]
    float2* hp  = (float2*)(smem + IN_DIM * OUT_DIM);   // [64 pairs][256 k]

    const int t    = threadIdx.x;
    const int row0 = blockIdx.x * TILE_M;

    #pragma unroll 4
    for (int i = t; i < IN_DIM * OUT_DIM; i += 512) Wsh[i] = W[i];

    for (int i = t; i < TILE_M * (IN_DIM / 4); i += 512) {
        int r  = i / (IN_DIM / 4);
        int k4 = i % (IN_DIM / 4);
        int gr = row0 + r;
        float4 v = (gr < N_NODES) ? ((const float4*)h)[gr * (IN_DIM / 4) + k4]
                                  : make_float4(0.f, 0.f, 0.f, 0.f);
        int p = r >> 1, half = r & 1;
        float* dst = (float*)&hp[p * IN_DIM + k4 * 4];
        dst[0 * 2 + half] = v.x;
        dst[1 * 2 + half] = v.y;
        dst[2 * 2 + half] = v.z;
        dst[3 * 2 + half] = v.w;
    }
    __syncthreads();

    const int c0   = (t & 31) * 2;
    const int pr0  = (t >> 5) * 4;       // 16 warps x 4 pairs = 64 pairs = 128 rows
    const int lane = t & 31;

    ull acc[4][2];
    #pragma unroll
    for (int p = 0; p < 4; p++) { acc[p][0] = 0ULL; acc[p][1] = 0ULL; }

    #pragma unroll 2
    for (int k0 = 0; k0 < IN_DIM; k0 += 2) {
        float2 wA = *(const float2*)&Wsh[k0 * OUT_DIM + c0];
        float2 wB = *(const float2*)&Wsh[(k0 + 1) * OUT_DIM + c0];
        ull b00, b01, b10, b11;
        asm("mov.b64 %0, {%1, %1};" : "=l"(b00) : "r"(__float_as_uint(wA.x)));
        asm("mov.b64 %0, {%1, %1};" : "=l"(b01) : "r"(__float_as_uint(wA.y)));
        asm("mov.b64 %0, {%1, %1};" : "=l"(b10) : "r"(__float_as_uint(wB.x)));
        asm("mov.b64 %0, {%1, %1};" : "=l"(b11) : "r"(__float_as_uint(wB.y)));
        #pragma unroll
        for (int p = 0; p < 4; p++) {
            ulonglong2 vv = *(const ulonglong2*)&hp[(pr0 + p) * IN_DIM + k0];
            asm("fma.rn.f32x2 %0, %1, %2, %0;" : "+l"(acc[p][0]) : "l"(vv.x), "l"(b00));
            asm("fma.rn.f32x2 %0, %1, %2, %0;" : "+l"(acc[p][1]) : "l"(vv.x), "l"(b01));
            asm("fma.rn.f32x2 %0, %1, %2, %0;" : "+l"(acc[p][0]) : "l"(vv.y), "l"(b10));
            asm("fma.rn.f32x2 %0, %1, %2, %0;" : "+l"(acc[p][1]) : "l"(vv.y), "l"(b11));
        }
    }

    // ---- fused s_l / s_r: per-pair partials, butterfly over 32 lanes ----
    const float al0 = __ldg(&a_attn[c0]),      al1 = __ldg(&a_attn[c0 + 1]);
    const float ar0 = __ldg(&a_attn[64 + c0]), ar1 = __ldg(&a_attn[64 + c0 + 1]);
    ull slp[4], srp[4];
    #pragma unroll
    for (int p = 0; p < 4; p++) {
        float2 a0 = *(float2*)&acc[p][0];   // (z[r][c0], z[r+1][c0])
        float2 a1 = *(float2*)&acc[p][1];   // (z[r][c1], z[r+1][c1])
        float2 sl2 = make_float2(a0.x * al0 + a1.x * al1, a0.y * al0 + a1.y * al1);
        float2 sr2 = make_float2(a0.x * ar0 + a1.x * ar1, a0.y * ar0 + a1.y * ar1);
        slp[p] = *(ull*)&sl2;
        srp[p] = *(ull*)&sr2;
    }
    #pragma unroll
    for (int o = 16; o; o >>= 1) {
        #pragma unroll
        for (int p = 0; p < 4; p++) {
            ull ya = __shfl_xor_sync(0xffffffffu, slp[p], o);
            ull yb = __shfl_xor_sync(0xffffffffu, srp[p], o);
            ADD2(slp[p], ya);
            ADD2(srp[p], yb);
        }
    }
    if (lane == 0) {
        #pragma unroll
        for (int p = 0; p < 4; p++) {
            int r0 = row0 + 2 * (pr0 + p);
            float2 sl2 = *(float2*)&slp[p];
            float2 sr2 = *(float2*)&srp[p];
            if (r0 < N_NODES)     { g_sl[r0]     = sl2.x; g_sr[r0]     = sr2.x; }
            if (r0 + 1 < N_NODES) { g_sl[r0 + 1] = sl2.y; g_sr[r0 + 1] = sr2.y; }
        }
    }

    #pragma unroll
    for (int p = 0; p < 4; p++) {
        int r0 = row0 + 2 * (pr0 + p);
        float2 a0 = *(float2*)&acc[p][0];
        float2 a1 = *(float2*)&acc[p][1];
        if (r0 < N_NODES)     *(float2*)&g_z[r0 * OUT_DIM + c0]       = make_float2(a0.x, a1.x);
        if (r0 + 1 < N_NODES) *(float2*)&g_z[(r0 + 1) * OUT_DIM + c0] = make_float2(a0.y, a1.y);
    }
}

// ---------------- zero histogram + denominators ----------------
__global__ void zero_kernel() {
    int i = blockIdx.x * blockDim.x + threadIdx.x;
    if (i <= N_NODES) g_off[i] = 0;
    if (i < N_NODES)  g_den[i] = 0.f;
}

// ---------------- histogram (4 edges/thread) ----------------
__global__ void hist_kernel(const int* __restrict__ edge_dst) {
    int i = blockIdx.x * blockDim.x + threadIdx.x;
    if (i * 4 >= N_EDGES) return;
    int4 d = ((const int4*)edge_dst)[i];
    atomicAdd(&g_off[d.x + 1], 1);
    atomicAdd(&g_off[d.y + 1], 1);
    atomicAdd(&g_off[d.z + 1], 1);
    atomicAdd(&g_off[d.w + 1], 1);
}

// ---------------- thread-coarsened single-block scan ----------------
__global__ void scan_kernel() {
    const int C = 49;
    __shared__ int wsum[32];
    const int t = threadIdx.x, lane = t & 31, w = t >> 5;
    const int base = 1 + t * C;
    int s = 0;
    #pragma unroll
    for (int i = 0; i < C; i++) {
        int idx = base + i;
        s += (idx <= N_NODES) ? g_off[idx] : 0;
    }
    int x = s;
    #pragma unroll
    for (int o = 1; o < 32; o <<= 1) {
        int y = __shfl_up_sync(0xffffffffu, x, o);
        if (lane >= o) x += y;
    }
    if (lane == 31) wsum[w] = x;
    __syncthreads();
    if (w == 0) {
        int v = wsum[lane];
        #pragma unroll
        for (int o = 1; o < 32; o <<= 1) {
            int y = __shfl_up_sync(0xffffffffu, v, o);
            if (lane >= o) v += y;
        }
        wsum[lane] = v;
    }
    __syncthreads();
    int run = x - s + ((w > 0) ? wsum[w - 1] : 0);
    #pragma unroll
    for (int i = 0; i < C; i++) {
        int idx = base + i;
        if (idx <= N_NODES) {
            int cnt = g_off[idx];
            g_cur[idx - 1] = run;
            run += cnt;
            g_off[idx] = run;
        }
    }
}

// ---------------- scatter: 4 edges/thread, packed exp(e)|src + den atomics ----------------
__global__ void scatter_kernel(const int* __restrict__ edge_src,
                               const int* __restrict__ edge_dst) {
    int i = blockIdx.x * blockDim.x + threadIdx.x;
    if (i * 4 >= N_EDGES) return;
    int4 s4 = ((const int4*)edge_src)[i];
    int4 d4 = ((const int4*)edge_dst)[i];
    float e0 = g_sl[s4.x] + g_sr[d4.x];
    float e1 = g_sl[s4.y] + g_sr[d4.y];
    float e2 = g_sl[s4.z] + g_sr[d4.z];
    float e3 = g_sl[s4.w] + g_sr[d4.w];
    e0 = (e0 > 0.f) ? e0 : NEG_SLOPE * e0;
    e1 = (e1 > 0.f) ? e1 : NEG_SLOPE * e1;
    e2 = (e2 > 0.f) ? e2 : NEG_SLOPE * e2;
    e3 = (e3 > 0.f) ? e3 : NEG_SLOPE * e3;
    float x0 = __expf(e0), x1 = __expf(e1), x2 = __expf(e2), x3 = __expf(e3);
    int p0 = atomicAdd(&g_cur[d4.x], 1);
    int p1 = atomicAdd(&g_cur[d4.y], 1);
    int p2 = atomicAdd(&g_cur[d4.z], 1);
    int p3 = atomicAdd(&g_cur[d4.w], 1);
    g_ep[p0] = ((ull)__float_as_uint(x0) << 32) | (unsigned)s4.x;
    g_ep[p1] = ((ull)__float_as_uint(x1) << 32) | (unsigned)s4.y;
    g_ep[p2] = ((ull)__float_as_uint(x2) << 32) | (unsigned)s4.z;
    g_ep[p3] = ((ull)__float_as_uint(x3) << 32) | (unsigned)s4.w;
    atomicAdd(&g_den[d4.x], x0);
    atomicAdd(&g_den[d4.y], x1);
    atomicAdd(&g_den[d4.z], x2);
    atomicAdd(&g_den[d4.w], x3);
}

// ---------------- node phase: one warp per dst, single pass, unroll 4 ----------------
__global__ void node_kernel(float* __restrict__ out) {
    int gw   = (blockIdx.x * blockDim.x + threadIdx.x) >> 5;
    int lane = threadIdx.x & 31;
    if (gw >= N_NODES) return;
    int beg = g_off[gw];
    int end = g_off[gw + 1];

    float2 acc = make_float2(0.f, 0.f);
    if (beg < end) {
        float invden = 1.0f / g_den[gw];
        int j = beg;
        for (; j + 3 < end; j += 4) {
            ull v0 = g_ep[j],     v1 = g_ep[j + 1];
            ull v2 = g_ep[j + 2], v3 = g_ep[j + 3];
            int s0 = (int)(v0 & 0xffffffffu), s1 = (int)(v1 & 0xffffffffu);
            int s2 = (int)(v2 & 0xffffffffu), s3 = (int)(v3 & 0xffffffffu);
            float2 z0 = *(const float2*)&g_z[s0 * OUT_DIM + 2 * lane];
            float2 z1 = *(const float2*)&g_z[s1 * OUT_DIM + 2 * lane];
            float2 z2 = *(const float2*)&g_z[s2 * OUT_DIM + 2 * lane];
            float2 z3 = *(const float2*)&g_z[s3 * OUT_DIM + 2 * lane];
            float a0 = __uint_as_float((uint32_t)(v0 >> 32)) * invden;
            float a1 = __uint_as_float((uint32_t)(v1 >> 32)) * invden;
            float a2 = __uint_as_float((uint32_t)(v2 >> 32)) * invden;
            float a3 = __uint_as_float((uint32_t)(v3 >> 32)) * invden;
            acc.x += a0 * z0.x + a1 * z1.x + a2 * z2.x + a3 * z3.x;
            acc.y += a0 * z0.y + a1 * z1.y + a2 * z2.y + a3 * z3.y;
        }
        for (; j < end; ++j) {
            ull v0 = g_ep[j];
            int s0 = (int)(v0 & 0xffffffffu);
            float a0 = __uint_as_float((uint32_t)(v0 >> 32)) * invden;
            float2 z0 = *(const float2*)&g_z[s0 * OUT_DIM + 2 * lane];
            acc.x += a0 * z0.x;
            acc.y += a0 * z0.y;
        }
    }
    *(float2*)&out[gw * OUT_DIM + 2 * lane] = acc;
}

// ---------------- launch: fork-join two streams inside capture ----------------
extern "C" void kernel_launch(void* const* d_in, const int* in_sizes, int n_in,
                              void* d_out, int out_size) {
    const float* h        = (const float*)d_in[0];
    const int*   edge_src = (const int*)d_in[1];
    const int*   edge_dst = (const int*)d_in[2];
    const float* W_fc     = (const float*)d_in[3];
    const float* a_attn   = (const float*)d_in[4];
    float* out = (float*)d_out;

    static cudaStream_t sB = nullptr;
    static cudaEvent_t  evFork = nullptr, evJoin = nullptr;
    if (!sB) {
        cudaStreamCreateWithFlags(&sB, cudaStreamNonBlocking);
        cudaEventCreateWithFlags(&evFork, cudaEventDisableTiming);
        cudaEventCreateWithFlags(&evJoin, cudaEventDisableTiming);
        const int SMEM = (IN_DIM * OUT_DIM) * 4 + (TILE_M / 2) * IN_DIM * 8;
        cudaFuncSetAttribute(gemm_kernel, cudaFuncAttributeMaxDynamicSharedMemorySize, SMEM);
    }
    const int SMEM = (IN_DIM * OUT_DIM) * 4 + (TILE_M / 2) * IN_DIM * 8; // 192KB

    // fork: stream B handles the edge-dst-only CSR build
    cudaEventRecord(evFork, 0);
    cudaStreamWaitEvent(sB, evFork, 0);

    zero_kernel<<<(N_NODES + 256) / 256, 256, 0, sB>>>();
    hist_kernel<<<(N_EDGES / 4 + 255) / 256, 256, 0, sB>>>(edge_dst);
    scan_kernel<<<1, 1024, 0, sB>>>();
    cudaEventRecord(evJoin, sB);

    // main stream: gemm with fused s_l/s_r
    gemm_kernel<<<(N_NODES + TILE_M - 1) / TILE_M, 512, SMEM>>>(h, W_fc, a_attn);

    // join, then the dependent tail
    cudaStreamWaitEvent(0, evJoin, 0);
    scatter_kernel<<<(N_EDGES / 4 + 255) / 256, 256>>>(edge_src, edge_dst);
    node_kernel<<<(N_NODES * 32 + 255) / 256, 256>>>(out);
}

// round 8
// speedup vs baseline: 1.1105x; 1.1105x over previous
#include <cuda_runtime.h>
#include <cuda_bf16.h>
#include <cstdint>

#define N_NODES 50000
#define N_EDGES 800000
#define IN_DIM  256
#define OUT_DIM 64
#define NEG_SLOPE 0.01f
#define TILE_M 128

typedef unsigned long long ull;

// ---------------- device scratch ----------------
__device__ float g_z[N_NODES * OUT_DIM];     // 12.8 MB, L2-resident
__device__ float g_sl[N_NODES];
__device__ float g_sr[N_NODES];
__device__ float g_den[N_NODES];             // softmax denominators (atomic)
__device__ int   g_off[N_NODES + 1];         // CSR offsets (by dst)
__device__ int   g_cur[N_NODES];             // scatter cursors
__device__ ull   g_ep[N_EDGES];              // packed (exp(e)<<32 | src), dst-sorted

__device__ __forceinline__ uint32_t smem_u32(const void* p) {
    uint32_t a;
    asm("{ .reg .u64 t; cvta.to.shared.u64 t, %1; cvt.u32.u64 %0, t; }" : "=r"(a) : "l"(p));
    return a;
}

#define LDSM4(R, addr) \
    asm volatile("ldmatrix.sync.aligned.m8n8.x4.shared.b16 {%0,%1,%2,%3}, [%4];" \
        : "=r"((R)[0]), "=r"((R)[1]), "=r"((R)[2]), "=r"((R)[3]) : "r"(addr))
#define LDSM4T(R, addr) \
    asm volatile("ldmatrix.sync.aligned.m8n8.x4.trans.shared.b16 {%0,%1,%2,%3}, [%4];" \
        : "=r"((R)[0]), "=r"((R)[1]), "=r"((R)[2]), "=r"((R)[3]) : "r"(addr))
#define MMA16816(D, A, b0, b1) \
    asm volatile("mma.sync.aligned.m16n8k16.row.col.f32.bf16.bf16.f32 " \
        "{%0,%1,%2,%3}, {%4,%5,%6,%7}, {%8,%9}, {%0,%1,%2,%3};" \
        : "+f"((D)[0]), "+f"((D)[1]), "+f"((D)[2]), "+f"((D)[3]) \
        : "r"((A)[0]), "r"((A)[1]), "r"((A)[2]), "r"((A)[3]), "r"(b0), "r"(b1))

// ---------------- SMEM layout (bytes) ----------------
// A tiles: 128 rows x 264 bf16 (stride 528B -> +16B/row, ldmatrix conflict-free)
// W tiles: 256 rows x 72 bf16  (stride 144B -> +16B/row)
#define A_STRIDE_B 528
#define W_STRIDE_B 144
#define SM_AHI   0
#define SM_ALO   67584
#define SM_WHI   135168
#define SM_WLO   172032
#define SM_TOTAL 208896

// ---------------- GEMM: z = h @ W via mma.sync bf16x3 + fused s_l/s_r ----------------
// 256 threads = 8 warps; warp w owns rows [16w, 16w+16) of the 128-row tile.
__global__ void __launch_bounds__(256, 1) gemm_kernel(const float* __restrict__ h,
                                                      const float* __restrict__ W,
                                                      const float* __restrict__ a_attn) {
    extern __shared__ char smem[];
    const uint32_t sb = smem_u32(smem);
    const int t = threadIdx.x, wid = t >> 5, lane = t & 31;
    const int row0 = blockIdx.x * TILE_M;

    // ---- convert h tile to bf16 hi/lo in smem ----
    for (int i = t; i < TILE_M * (IN_DIM / 4); i += 256) {
        int r = i >> 6, k4 = i & 63;
        int gr = row0 + r;
        float4 v = (gr < N_NODES) ? ((const float4*)h)[gr * (IN_DIM / 4) + k4]
                                  : make_float4(0.f, 0.f, 0.f, 0.f);
        __nv_bfloat162 h01 = __floats2bfloat162_rn(v.x, v.y);
        __nv_bfloat162 h23 = __floats2bfloat162_rn(v.z, v.w);
        __nv_bfloat162 l01 = __floats2bfloat162_rn(v.x - __bfloat162float(h01.x),
                                                   v.y - __bfloat162float(h01.y));
        __nv_bfloat162 l23 = __floats2bfloat162_rn(v.z - __bfloat162float(h23.x),
                                                   v.w - __bfloat162float(h23.y));
        uint32_t off = (uint32_t)r * A_STRIDE_B + k4 * 8;
        *(uint2*)(smem + SM_AHI + off) = make_uint2(*(uint32_t*)&h01, *(uint32_t*)&h23);
        *(uint2*)(smem + SM_ALO + off) = make_uint2(*(uint32_t*)&l01, *(uint32_t*)&l23);
    }
    // ---- convert W to bf16 hi/lo in smem ----
    for (int i = t; i < IN_DIM * OUT_DIM; i += 256) {
        int k = i >> 6, n = i & 63;
        float w = W[i];
        __nv_bfloat16 wh = __float2bfloat16(w);
        __nv_bfloat16 wl = __float2bfloat16(w - __bfloat162float(wh));
        *(__nv_bfloat16*)(smem + SM_WHI + k * W_STRIDE_B + n * 2) = wh;
        *(__nv_bfloat16*)(smem + SM_WLO + k * W_STRIDE_B + n * 2) = wl;
    }
    __syncthreads();

    // ---- mma mainloop ----
    const int m0 = wid * 16;
    const int lr = lane & 7, lh = (lane >> 3) & 1, lq = lane >> 4;

    // A: lanes 0-7 rows 0-7 @k0, 8-15 rows 8-15 @k0, 16-23 rows 0-7 @k+8, 24-31 rows 8-15 @k+8
    uint32_t aHi = sb + SM_AHI + (uint32_t)(m0 + lr + lh * 8) * A_STRIDE_B + lq * 16;
    uint32_t aLo = aHi + (SM_ALO - SM_AHI);
    // B (trans): lanes 0-7 k-rows 0-7 @n0, 8-15 k-rows 8-15 @n0, 16-31 same @n0+8
    uint32_t bHi = sb + SM_WHI + (uint32_t)(lr + lh * 8) * W_STRIDE_B + lq * 16;
    uint32_t bLo = bHi + (SM_WLO - SM_WHI);

    float d[8][4];
    #pragma unroll
    for (int i = 0; i < 8; i++)
        #pragma unroll
        for (int j = 0; j < 4; j++) d[i][j] = 0.f;

    #pragma unroll 2
    for (int kc = 0; kc < 16; kc++) {
        uint32_t ah[4], al[4];
        LDSM4(ah, aHi + kc * 32);
        LDSM4(al, aLo + kc * 32);
        uint32_t bh[4][4], bl[4][4];
        #pragma unroll
        for (int j = 0; j < 4; j++) {
            LDSM4T(bh[j], bHi + kc * (16 * W_STRIDE_B) + j * 32);
            LDSM4T(bl[j], bLo + kc * (16 * W_STRIDE_B) + j * 32);
        }
        #pragma unroll
        for (int j = 0; j < 4; j++) {
            MMA16816(d[2 * j],     ah, bh[j][0], bh[j][1]);   // hi*hi
            MMA16816(d[2 * j],     ah, bl[j][0], bl[j][1]);   // hi*lo
            MMA16816(d[2 * j],     al, bh[j][0], bh[j][1]);   // lo*hi
            MMA16816(d[2 * j + 1], ah, bh[j][2], bh[j][3]);
            MMA16816(d[2 * j + 1], ah, bl[j][2], bl[j][3]);
            MMA16816(d[2 * j + 1], al, bh[j][2], bh[j][3]);
        }
    }

    // ---- epilogue: write z + fused s_l/s_r ----
    // D frag: lane q=lane/4 -> rows q and q+8; cols 2*(lane%4)+{0,1} per n-tile
    const int q = lane >> 2, cq = (lane & 3) * 2;
    const int r1 = row0 + m0 + q, r2 = r1 + 8;
    float sl1 = 0.f, sr1 = 0.f, sl2 = 0.f, sr2 = 0.f;
    #pragma unroll
    for (int i = 0; i < 8; i++) {
        int c = i * 8 + cq;
        float a0 = __ldg(&a_attn[c]),      a1 = __ldg(&a_attn[c + 1]);
        float b0 = __ldg(&a_attn[64 + c]), b1 = __ldg(&a_attn[64 + c + 1]);
        sl1 += d[i][0] * a0 + d[i][1] * a1;
        sr1 += d[i][0] * b0 + d[i][1] * b1;
        sl2 += d[i][2] * a0 + d[i][3] * a1;
        sr2 += d[i][2] * b0 + d[i][3] * b1;
        if (r1 < N_NODES) *(float2*)&g_z[r1 * OUT_DIM + c] = make_float2(d[i][0], d[i][1]);
        if (r2 < N_NODES) *(float2*)&g_z[r2 * OUT_DIM + c] = make_float2(d[i][2], d[i][3]);
    }
    #pragma unroll
    for (int o = 1; o < 4; o <<= 1) {
        sl1 += __shfl_xor_sync(0xffffffffu, sl1, o);
        sr1 += __shfl_xor_sync(0xffffffffu, sr1, o);
        sl2 += __shfl_xor_sync(0xffffffffu, sl2, o);
        sr2 += __shfl_xor_sync(0xffffffffu, sr2, o);
    }
    if ((lane & 3) == 0) {
        if (r1 < N_NODES) { g_sl[r1] = sl1; g_sr[r1] = sr1; }
        if (r2 < N_NODES) { g_sl[r2] = sl2; g_sr[r2] = sr2; }
    }
}

// ---------------- zero histogram + denominators ----------------
__global__ void zero_kernel() {
    int i = blockIdx.x * blockDim.x + threadIdx.x;
    if (i <= N_NODES) g_off[i] = 0;
    if (i < N_NODES)  g_den[i] = 0.f;
}

// ---------------- histogram (4 edges/thread) ----------------
__global__ void hist_kernel(const int* __restrict__ edge_dst) {
    int i = blockIdx.x * blockDim.x + threadIdx.x;
    if (i * 4 >= N_EDGES) return;
    int4 d = ((const int4*)edge_dst)[i];
    atomicAdd(&g_off[d.x + 1], 1);
    atomicAdd(&g_off[d.y + 1], 1);
    atomicAdd(&g_off[d.z + 1], 1);
    atomicAdd(&g_off[d.w + 1], 1);
}

// ---------------- thread-coarsened single-block scan ----------------
__global__ void scan_kernel() {
    const int C = 49;
    __shared__ int wsum[32];
    const int t = threadIdx.x, lane = t & 31, w = t >> 5;
    const int base = 1 + t * C;
    int s = 0;
    #pragma unroll
    for (int i = 0; i < C; i++) {
        int idx = base + i;
        s += (idx <= N_NODES) ? g_off[idx] : 0;
    }
    int x = s;
    #pragma unroll
    for (int o = 1; o < 32; o <<= 1) {
        int y = __shfl_up_sync(0xffffffffu, x, o);
        if (lane >= o) x += y;
    }
    if (lane == 31) wsum[w] = x;
    __syncthreads();
    if (w == 0) {
        int v = wsum[lane];
        #pragma unroll
        for (int o = 1; o < 32; o <<= 1) {
            int y = __shfl_up_sync(0xffffffffu, v, o);
            if (lane >= o) v += y;
        }
        wsum[lane] = v;
    }
    __syncthreads();
    int run = x - s + ((w > 0) ? wsum[w - 1] : 0);
    #pragma unroll
    for (int i = 0; i < C; i++) {
        int idx = base + i;
        if (idx <= N_NODES) {
            int cnt = g_off[idx];
            g_cur[idx - 1] = run;
            run += cnt;
            g_off[idx] = run;
        }
    }
}

// ---------------- scatter: 4 edges/thread, packed exp(e)|src + den atomics ----------------
__global__ void scatter_kernel(const int* __restrict__ edge_src,
                               const int* __restrict__ edge_dst) {
    int i = blockIdx.x * blockDim.x + threadIdx.x;
    if (i * 4 >= N_EDGES) return;
    int4 s4 = ((const int4*)edge_src)[i];
    int4 d4 = ((const int4*)edge_dst)[i];
    float e0 = g_sl[s4.x] + g_sr[d4.x];
    float e1 = g_sl[s4.y] + g_sr[d4.y];
    float e2 = g_sl[s4.z] + g_sr[d4.z];
    float e3 = g_sl[s4.w] + g_sr[d4.w];
    e0 = (e0 > 0.f) ? e0 : NEG_SLOPE * e0;
    e1 = (e1 > 0.f) ? e1 : NEG_SLOPE * e1;
    e2 = (e2 > 0.f) ? e2 : NEG_SLOPE * e2;
    e3 = (e3 > 0.f) ? e3 : NEG_SLOPE * e3;
    float x0 = __expf(e0), x1 = __expf(e1), x2 = __expf(e2), x3 = __expf(e3);
    int p0 = atomicAdd(&g_cur[d4.x], 1);
    int p1 = atomicAdd(&g_cur[d4.y], 1);
    int p2 = atomicAdd(&g_cur[d4.z], 1);
    int p3 = atomicAdd(&g_cur[d4.w], 1);
    g_ep[p0] = ((ull)__float_as_uint(x0) << 32) | (unsigned)s4.x;
    g_ep[p1] = ((ull)__float_as_uint(x1) << 32) | (unsigned)s4.y;
    g_ep[p2] = ((ull)__float_as_uint(x2) << 32) | (unsigned)s4.z;
    g_ep[p3] = ((ull)__float_as_uint(x3) << 32) | (unsigned)s4.w;
    atomicAdd(&g_den[d4.x], x0);
    atomicAdd(&g_den[d4.y], x1);
    atomicAdd(&g_den[d4.z], x2);
    atomicAdd(&g_den[d4.w], x3);
}

// ---------------- node phase: one warp per dst, single pass, unroll 4 ----------------
__global__ void node_kernel(float* __restrict__ out) {
    int gw   = (blockIdx.x * blockDim.x + threadIdx.x) >> 5;
    int lane = threadIdx.x & 31;
    if (gw >= N_NODES) return;
    int beg = g_off[gw];
    int end = g_off[gw + 1];

    float2 acc = make_float2(0.f, 0.f);
    if (beg < end) {
        float invden = 1.0f / g_den[gw];
        int j = beg;
        for (; j + 3 < end; j += 4) {
            ull v0 = g_ep[j],     v1 = g_ep[j + 1];
            ull v2 = g_ep[j + 2], v3 = g_ep[j + 3];
            int s0 = (int)(v0 & 0xffffffffu), s1 = (int)(v1 & 0xffffffffu);
            int s2 = (int)(v2 & 0xffffffffu), s3 = (int)(v3 & 0xffffffffu);
            float2 z0 = *(const float2*)&g_z[s0 * OUT_DIM + 2 * lane];
            float2 z1 = *(const float2*)&g_z[s1 * OUT_DIM + 2 * lane];
            float2 z2 = *(const float2*)&g_z[s2 * OUT_DIM + 2 * lane];
            float2 z3 = *(const float2*)&g_z[s3 * OUT_DIM + 2 * lane];
            float a0 = __uint_as_float((uint32_t)(v0 >> 32)) * invden;
            float a1 = __uint_as_float((uint32_t)(v1 >> 32)) * invden;
            float a2 = __uint_as_float((uint32_t)(v2 >> 32)) * invden;
            float a3 = __uint_as_float((uint32_t)(v3 >> 32)) * invden;
            acc.x += a0 * z0.x + a1 * z1.x + a2 * z2.x + a3 * z3.x;
            acc.y += a0 * z0.y + a1 * z1.y + a2 * z2.y + a3 * z3.y;
        }
        for (; j < end; ++j) {
            ull v0 = g_ep[j];
            int s0 = (int)(v0 & 0xffffffffu);
            float a0 = __uint_as_float((uint32_t)(v0 >> 32)) * invden;
            float2 z0 = *(const float2*)&g_z[s0 * OUT_DIM + 2 * lane];
            acc.x += a0 * z0.x;
            acc.y += a0 * z0.y;
        }
    }
    *(float2*)&out[gw * OUT_DIM + 2 * lane] = acc;
}

// ---------------- launch: fork-join two streams inside capture ----------------
extern "C" void kernel_launch(void* const* d_in, const int* in_sizes, int n_in,
                              void* d_out, int out_size) {
    const float* h        = (const float*)d_in[0];
    const int*   edge_src = (const int*)d_in[1];
    const int*   edge_dst = (const int*)d_in[2];
    const float* W_fc     = (const float*)d_in[3];
    const float* a_attn   = (const float*)d_in[4];
    float* out = (float*)d_out;

    static cudaStream_t sB = nullptr;
    static cudaEvent_t  evFork = nullptr, evJoin = nullptr;
    if (!sB) {
        cudaStreamCreateWithFlags(&sB, cudaStreamNonBlocking);
        cudaEventCreateWithFlags(&evFork, cudaEventDisableTiming);
        cudaEventCreateWithFlags(&evJoin, cudaEventDisableTiming);
        cudaFuncSetAttribute(gemm_kernel, cudaFuncAttributeMaxDynamicSharedMemorySize, SM_TOTAL);
    }

    // fork: stream B handles the edge-dst-only CSR build
    cudaEventRecord(evFork, 0);
    cudaStreamWaitEvent(sB, evFork, 0);

    zero_kernel<<<(N_NODES + 256) / 256, 256, 0, sB>>>();
    hist_kernel<<<(N_EDGES / 4 + 255) / 256, 256, 0, sB>>>(edge_dst);
    scan_kernel<<<1, 1024, 0, sB>>>();
    cudaEventRecord(evJoin, sB);

    // main stream: gemm with fused s_l/s_r
    gemm_kernel<<<(N_NODES + TILE_M - 1) / TILE_M, 256, SM_TOTAL>>>(h, W_fc, a_attn);

    // join, then the dependent tail
    cudaStreamWaitEvent(0, evJoin, 0);
    scatter_kernel<<<(N_EDGES / 4 + 255) / 256, 256>>>(edge_src, edge_dst);
    node_kernel<<<(N_NODES * 32 + 255) / 256, 256>>>(out);
}

// round 9
// speedup vs baseline: 1.3216x; 1.1901x over previous
#include <cuda_runtime.h>
#include <cuda_bf16.h>
#include <cstdint>

#define N_NODES 50000
#define N_EDGES 800000
#define IN_DIM  256
#define OUT_DIM 64
#define NEG_SLOPE 0.01f
#define TILE_M 64

typedef unsigned long long ull;

// ---------------- device scratch ----------------
__device__ float g_z[N_NODES * OUT_DIM];     // 12.8 MB, L2-resident
__device__ float g_sl[N_NODES];
__device__ float g_sr[N_NODES];
__device__ float g_den[N_NODES];
__device__ int   g_off[N_NODES + 1];
__device__ int   g_cur[N_NODES];
__device__ ull   g_ep[N_EDGES];
__device__ __nv_bfloat16 g_wh[IN_DIM * OUT_DIM];   // W hi (bf16), row-major [k][n]
__device__ __nv_bfloat16 g_wl[IN_DIM * OUT_DIM];   // W lo

__device__ __forceinline__ uint32_t smem_u32(const void* p) {
    uint32_t a;
    asm("{ .reg .u64 t; cvta.to.shared.u64 t, %1; cvt.u32.u64 %0, t; }" : "=r"(a) : "l"(p));
    return a;
}

#define LDSM4(R, addr) \
    asm volatile("ldmatrix.sync.aligned.m8n8.x4.shared.b16 {%0,%1,%2,%3}, [%4];" \
        : "=r"((R)[0]), "=r"((R)[1]), "=r"((R)[2]), "=r"((R)[3]) : "r"(addr))
#define LDSM4T(R, addr) \
    asm volatile("ldmatrix.sync.aligned.m8n8.x4.trans.shared.b16 {%0,%1,%2,%3}, [%4];" \
        : "=r"((R)[0]), "=r"((R)[1]), "=r"((R)[2]), "=r"((R)[3]) : "r"(addr))
#define MMA16816(D, A, b0, b1) \
    asm volatile("mma.sync.aligned.m16n8k16.row.col.f32.bf16.bf16.f32 " \
        "{%0,%1,%2,%3}, {%4,%5,%6,%7}, {%8,%9}, {%0,%1,%2,%3};" \
        : "+f"((D)[0]), "+f"((D)[1]), "+f"((D)[2]), "+f"((D)[3]) \
        : "r"((A)[0]), "r"((A)[1]), "r"((A)[2]), "r"((A)[3]), "r"(b0), "r"(b1))

// ---------------- SMEM layout (bytes) ----------------
// W: 256 rows x 72 bf16 (stride 144B, +16B pad) hi/lo
// A chunk: 64 rows x 136 bf16 (stride 272B, +16B pad) hi/lo  [K-chunk of 128]
#define W_STRIDE_B 144
#define A_STRIDE_B 272
#define SM_WHI   0
#define SM_WLO   36864
#define SM_AHI   73728
#define SM_ALO   91136
#define SM_SLR   108544      // 64 rows x 2 n-halves x (sl,sr) floats = 1024 B
#define SM_TOTAL 109568

// ---------------- W prep: fp32 -> bf16 hi/lo (once, to global) ----------------
__global__ void wprep_kernel(const float* __restrict__ W) {
    int i = blockIdx.x * blockDim.x + threadIdx.x;
    if (i >= IN_DIM * OUT_DIM) return;
    float w = W[i];
    __nv_bfloat16 wh = __float2bfloat16(w);
    __nv_bfloat16 wl = __float2bfloat16(w - __bfloat162float(wh));
    g_wh[i] = wh;
    g_wl[i] = wl;
}

// ---------------- GEMM: z = h @ W via mma.sync bf16x3, 2 CTA/SM ----------------
// 256 threads = 8 warps: warp = (m-tile wid&3) x (n-half wid>>2).
// TILE_M=64 rows/CTA, K in 2 chunks of 128 (A smem single-buffered per chunk).
__global__ void __launch_bounds__(256, 2) gemm_kernel(const float* __restrict__ h,
                                                      const float* __restrict__ a_attn) {
    extern __shared__ char smem[];
    const uint32_t sb = smem_u32(smem);
    const int t = threadIdx.x, wid = t >> 5, lane = t & 31;
    const int row0 = blockIdx.x * TILE_M;

    // ---- copy precomputed W hi/lo (bf16) into padded smem ----
    for (int i = t; i < 2048; i += 256) {           // 2048 uint4 = 32KB per matrix
        int r = i >> 3, u = i & 7;
        uint32_t off = (uint32_t)r * W_STRIDE_B + u * 16;
        *(uint4*)(smem + SM_WHI + off) = ((const uint4*)g_wh)[i];
        *(uint4*)(smem + SM_WLO + off) = ((const uint4*)g_wl)[i];
    }

    const int wm = wid & 3, wn = wid >> 2;
    const int m0 = wm * 16;
    const int lr = lane & 7, lh = (lane >> 3) & 1, lq = lane >> 4;

    const uint32_t aHiBase = sb + SM_AHI + (uint32_t)(m0 + lr + lh * 8) * A_STRIDE_B + lq * 16;
    const uint32_t aLoBase = aHiBase + (SM_ALO - SM_AHI);
    const uint32_t bHiBase = sb + SM_WHI + (uint32_t)(lr + lh * 8) * W_STRIDE_B + wn * 64 + lq * 16;
    const uint32_t bLoBase = bHiBase + (SM_WLO - SM_WHI);

    float d[4][4];
    #pragma unroll
    for (int i = 0; i < 4; i++)
        #pragma unroll
        for (int j = 0; j < 4; j++) d[i][j] = 0.f;

    #pragma unroll 1
    for (int chunk = 0; chunk < 2; chunk++) {
        // load A chunk: 64 rows x 128 cols fp32 -> bf16 hi/lo
        #pragma unroll
        for (int i = t; i < TILE_M * 32; i += 256) {
            int r = i >> 5, k4 = i & 31;
            int gr = row0 + r;
            float4 v = (gr < N_NODES)
                     ? ((const float4*)h)[gr * (IN_DIM / 4) + chunk * 32 + k4]
                     : make_float4(0.f, 0.f, 0.f, 0.f);
            __nv_bfloat162 h01 = __floats2bfloat162_rn(v.x, v.y);
            __nv_bfloat162 h23 = __floats2bfloat162_rn(v.z, v.w);
            __nv_bfloat162 l01 = __floats2bfloat162_rn(v.x - __bfloat162float(h01.x),
                                                       v.y - __bfloat162float(h01.y));
            __nv_bfloat162 l23 = __floats2bfloat162_rn(v.z - __bfloat162float(h23.x),
                                                       v.w - __bfloat162float(h23.y));
            uint32_t off = (uint32_t)r * A_STRIDE_B + k4 * 8;
            *(uint2*)(smem + SM_AHI + off) = make_uint2(*(uint32_t*)&h01, *(uint32_t*)&h23);
            *(uint2*)(smem + SM_ALO + off) = make_uint2(*(uint32_t*)&l01, *(uint32_t*)&l23);
        }
        __syncthreads();

        #pragma unroll 2
        for (int kcl = 0; kcl < 8; kcl++) {
            int kcg = chunk * 8 + kcl;
            uint32_t ah[4], al[4];
            LDSM4(ah, aHiBase + kcl * 32);
            LDSM4(al, aLoBase + kcl * 32);
            uint32_t bh[2][4], bl[2][4];
            #pragma unroll
            for (int j = 0; j < 2; j++) {
                LDSM4T(bh[j], bHiBase + kcg * (16 * W_STRIDE_B) + j * 32);
                LDSM4T(bl[j], bLoBase + kcg * (16 * W_STRIDE_B) + j * 32);
            }
            #pragma unroll
            for (int j = 0; j < 2; j++) {
                MMA16816(d[2 * j],     ah, bh[j][0], bh[j][1]);
                MMA16816(d[2 * j],     ah, bl[j][0], bl[j][1]);
                MMA16816(d[2 * j],     al, bh[j][0], bh[j][1]);
                MMA16816(d[2 * j + 1], ah, bh[j][2], bh[j][3]);
                MMA16816(d[2 * j + 1], ah, bl[j][2], bl[j][3]);
                MMA16816(d[2 * j + 1], al, bh[j][2], bh[j][3]);
            }
        }
        __syncthreads();   // before next chunk overwrites A
    }

    // ---- epilogue: write z + fused s_l/s_r ----
    float* slr = (float*)(smem + SM_SLR);   // [64][2 halves][2]
    const int q = lane >> 2, cq = (lane & 3) * 2;
    const int r1 = row0 + m0 + q, r2 = r1 + 8;
    float sl1 = 0.f, sr1 = 0.f, sl2 = 0.f, sr2 = 0.f;
    #pragma unroll
    for (int i = 0; i < 4; i++) {
        int c = wn * 32 + i * 8 + cq;
        float a0 = __ldg(&a_attn[c]),      a1 = __ldg(&a_attn[c + 1]);
        float b0 = __ldg(&a_attn[64 + c]), b1 = __ldg(&a_attn[64 + c + 1]);
        sl1 += d[i][0] * a0 + d[i][1] * a1;
        sr1 += d[i][0] * b0 + d[i][1] * b1;
        sl2 += d[i][2] * a0 + d[i][3] * a1;
        sr2 += d[i][2] * b0 + d[i][3] * b1;
        if (r1 < N_NODES) *(float2*)&g_z[r1 * OUT_DIM + c] = make_float2(d[i][0], d[i][1]);
        if (r2 < N_NODES) *(float2*)&g_z[r2 * OUT_DIM + c] = make_float2(d[i][2], d[i][3]);
    }
    #pragma unroll
    for (int o = 1; o < 4; o <<= 1) {
        sl1 += __shfl_xor_sync(0xffffffffu, sl1, o);
        sr1 += __shfl_xor_sync(0xffffffffu, sr1, o);
        sl2 += __shfl_xor_sync(0xffffffffu, sl2, o);
        sr2 += __shfl_xor_sync(0xffffffffu, sr2, o);
    }
    if ((lane & 3) == 0) {
        *(float2*)&slr[(m0 + q)     * 4 + wn * 2] = make_float2(sl1, sr1);
        *(float2*)&slr[(m0 + q + 8) * 4 + wn * 2] = make_float2(sl2, sr2);
    }
    __syncthreads();
    if (t < TILE_M) {
        int row = row0 + t;
        if (row < N_NODES) {
            g_sl[row] = slr[t * 4 + 0] + slr[t * 4 + 2];
            g_sr[row] = slr[t * 4 + 1] + slr[t * 4 + 3];
        }
    }
}

// ---------------- zero histogram + denominators ----------------
__global__ void zero_kernel() {
    int i = blockIdx.x * blockDim.x + threadIdx.x;
    if (i <= N_NODES) g_off[i] = 0;
    if (i < N_NODES)  g_den[i] = 0.f;
}

// ---------------- histogram (4 edges/thread) ----------------
__global__ void hist_kernel(const int* __restrict__ edge_dst) {
    int i = blockIdx.x * blockDim.x + threadIdx.x;
    if (i * 4 >= N_EDGES) return;
    int4 d = ((const int4*)edge_dst)[i];
    atomicAdd(&g_off[d.x + 1], 1);
    atomicAdd(&g_off[d.y + 1], 1);
    atomicAdd(&g_off[d.z + 1], 1);
    atomicAdd(&g_off[d.w + 1], 1);
}

// ---------------- thread-coarsened single-block scan ----------------
__global__ void scan_kernel() {
    const int C = 49;
    __shared__ int wsum[32];
    const int t = threadIdx.x, lane = t & 31, w = t >> 5;
    const int base = 1 + t * C;
    int s = 0;
    #pragma unroll
    for (int i = 0; i < C; i++) {
        int idx = base + i;
        s += (idx <= N_NODES) ? g_off[idx] : 0;
    }
    int x = s;
    #pragma unroll
    for (int o = 1; o < 32; o <<= 1) {
        int y = __shfl_up_sync(0xffffffffu, x, o);
        if (lane >= o) x += y;
    }
    if (lane == 31) wsum[w] = x;
    __syncthreads();
    if (w == 0) {
        int v = wsum[lane];
        #pragma unroll
        for (int o = 1; o < 32; o <<= 1) {
            int y = __shfl_up_sync(0xffffffffu, v, o);
            if (lane >= o) v += y;
        }
        wsum[lane] = v;
    }
    __syncthreads();
    int run = x - s + ((w > 0) ? wsum[w - 1] : 0);
    #pragma unroll
    for (int i = 0; i < C; i++) {
        int idx = base + i;
        if (idx <= N_NODES) {
            int cnt = g_off[idx];
            g_cur[idx - 1] = run;
            run += cnt;
            g_off[idx] = run;
        }
    }
}

// ---------------- scatter: 4 edges/thread, packed exp(e)|src + den atomics ----------------
__global__ void scatter_kernel(const int* __restrict__ edge_src,
                               const int* __restrict__ edge_dst) {
    int i = blockIdx.x * blockDim.x + threadIdx.x;
    if (i * 4 >= N_EDGES) return;
    int4 s4 = ((const int4*)edge_src)[i];
    int4 d4 = ((const int4*)edge_dst)[i];
    float e0 = g_sl[s4.x] + g_sr[d4.x];
    float e1 = g_sl[s4.y] + g_sr[d4.y];
    float e2 = g_sl[s4.z] + g_sr[d4.z];
    float e3 = g_sl[s4.w] + g_sr[d4.w];
    e0 = (e0 > 0.f) ? e0 : NEG_SLOPE * e0;
    e1 = (e1 > 0.f) ? e1 : NEG_SLOPE * e1;
    e2 = (e2 > 0.f) ? e2 : NEG_SLOPE * e2;
    e3 = (e3 > 0.f) ? e3 : NEG_SLOPE * e3;
    float x0 = __expf(e0), x1 = __expf(e1), x2 = __expf(e2), x3 = __expf(e3);
    int p0 = atomicAdd(&g_cur[d4.x], 1);
    int p1 = atomicAdd(&g_cur[d4.y], 1);
    int p2 = atomicAdd(&g_cur[d4.z], 1);
    int p3 = atomicAdd(&g_cur[d4.w], 1);
    g_ep[p0] = ((ull)__float_as_uint(x0) << 32) | (unsigned)s4.x;
    g_ep[p1] = ((ull)__float_as_uint(x1) << 32) | (unsigned)s4.y;
    g_ep[p2] = ((ull)__float_as_uint(x2) << 32) | (unsigned)s4.z;
    g_ep[p3] = ((ull)__float_as_uint(x3) << 32) | (unsigned)s4.w;
    atomicAdd(&g_den[d4.x], x0);
    atomicAdd(&g_den[d4.y], x1);
    atomicAdd(&g_den[d4.z], x2);
    atomicAdd(&g_den[d4.w], x3);
}

// ---------------- node phase: one warp per dst, single pass, unroll 4 ----------------
__global__ void node_kernel(float* __restrict__ out) {
    int gw   = (blockIdx.x * blockDim.x + threadIdx.x) >> 5;
    int lane = threadIdx.x & 31;
    if (gw >= N_NODES) return;
    int beg = g_off[gw];
    int end = g_off[gw + 1];

    float2 acc = make_float2(0.f, 0.f);
    if (beg < end) {
        float invden = 1.0f / g_den[gw];
        int j = beg;
        for (; j + 3 < end; j += 4) {
            ull v0 = g_ep[j],     v1 = g_ep[j + 1];
            ull v2 = g_ep[j + 2], v3 = g_ep[j + 3];
            int s0 = (int)(v0 & 0xffffffffu), s1 = (int)(v1 & 0xffffffffu);
            int s2 = (int)(v2 & 0xffffffffu), s3 = (int)(v3 & 0xffffffffu);
            float2 z0 = *(const float2*)&g_z[s0 * OUT_DIM + 2 * lane];
            float2 z1 = *(const float2*)&g_z[s1 * OUT_DIM + 2 * lane];
            float2 z2 = *(const float2*)&g_z[s2 * OUT_DIM + 2 * lane];
            float2 z3 = *(const float2*)&g_z[s3 * OUT_DIM + 2 * lane];
            float a0 = __uint_as_float((uint32_t)(v0 >> 32)) * invden;
            float a1 = __uint_as_float((uint32_t)(v1 >> 32)) * invden;
            float a2 = __uint_as_float((uint32_t)(v2 >> 32)) * invden;
            float a3 = __uint_as_float((uint32_t)(v3 >> 32)) * invden;
            acc.x += a0 * z0.x + a1 * z1.x + a2 * z2.x + a3 * z3.x;
            acc.y += a0 * z0.y + a1 * z1.y + a2 * z2.y + a3 * z3.y;
        }
        for (; j < end; ++j) {
            ull v0 = g_ep[j];
            int s0 = (int)(v0 & 0xffffffffu);
            float a0 = __uint_as_float((uint32_t)(v0 >> 32)) * invden;
            float2 z0 = *(const float2*)&g_z[s0 * OUT_DIM + 2 * lane];
            acc.x += a0 * z0.x;
            acc.y += a0 * z0.y;
        }
    }
    *(float2*)&out[gw * OUT_DIM + 2 * lane] = acc;
}

// ---------------- launch: fork-join two streams inside capture ----------------
extern "C" void kernel_launch(void* const* d_in, const int* in_sizes, int n_in,
                              void* d_out, int out_size) {
    const float* h        = (const float*)d_in[0];
    const int*   edge_src = (const int*)d_in[1];
    const int*   edge_dst = (const int*)d_in[2];
    const float* W_fc     = (const float*)d_in[3];
    const float* a_attn   = (const float*)d_in[4];
    float* out = (float*)d_out;

    static cudaStream_t sB = nullptr;
    static cudaEvent_t  evFork = nullptr, evJoin = nullptr;
    if (!sB) {
        cudaStreamCreateWithFlags(&sB, cudaStreamNonBlocking);
        cudaEventCreateWithFlags(&evFork, cudaEventDisableTiming);
        cudaEventCreateWithFlags(&evJoin, cudaEventDisableTiming);
        cudaFuncSetAttribute(gemm_kernel, cudaFuncAttributeMaxDynamicSharedMemorySize, SM_TOTAL);
    }

    // fork: stream B handles the edge-dst-only CSR build
    cudaEventRecord(evFork, 0);
    cudaStreamWaitEvent(sB, evFork, 0);

    zero_kernel<<<(N_NODES + 256) / 256, 256, 0, sB>>>();
    hist_kernel<<<(N_EDGES / 4 + 255) / 256, 256, 0, sB>>>(edge_dst);
    scan_kernel<<<1, 1024, 0, sB>>>();
    cudaEventRecord(evJoin, sB);

    // main stream: W prep then gemm with fused s_l/s_r
    wprep_kernel<<<(IN_DIM * OUT_DIM + 255) / 256, 256>>>(W_fc);
    gemm_kernel<<<(N_NODES + TILE_M - 1) / TILE_M, 256, SM_TOTAL>>>(h, a_attn);

    // join, then the dependent tail
    cudaStreamWaitEvent(0, evJoin, 0);
    scatter_kernel<<<(N_EDGES / 4 + 255) / 256, 256>>>(edge_src, edge_dst);
    node_kernel<<<(N_NODES * 32 + 255) / 256, 256>>>(out);
}